// round 5
// baseline (speedup 1.0000x reference)
#include <cuda_runtime.h>

// Fused 2-layer LSTM, H=6, B=4096, T=1024.
// 8 threads per batch element; lane role j = tid&7 owns hidden index j (j<6 active).
// Each thread computes all 4 gate rows {j, 6+j, 12+j, 18+j} for its j, so the
// cell update c[j], h[j] is thread-local; only h is exchanged (6 shfl / layer).
// Weights are register-resident, packed as f32x2 pairs; dot products use
// fma.rn.f32x2 (packed fp32 FMA, halves FFMA-pipe pressure).

#define T_STEPS 1024
#define BATCH   4096

__device__ __forceinline__ unsigned long long ffma2(unsigned long long a,
                                                    unsigned long long b,
                                                    unsigned long long c) {
    unsigned long long d;
    asm("fma.rn.f32x2 %0, %1, %2, %3;" : "=l"(d) : "l"(a), "l"(b), "l"(c));
    return d;
}

__device__ __forceinline__ unsigned long long pack2(float lo, float hi) {
    unsigned long long r;
    asm("mov.b64 %0, {%1, %2};" : "=l"(r) : "f"(lo), "f"(hi));
    return r;
}

__device__ __forceinline__ void unpack2(unsigned long long v, float& lo, float& hi) {
    asm("mov.b64 {%0, %1}, %2;" : "=f"(lo), "=f"(hi) : "l"(v));
}

// sigmoid(x) = 1/(1+e^-x). Safe at extremes: e->inf gives 0, e->0 gives 1.
__device__ __forceinline__ float sigmoid_f(float x) {
    return __fdividef(1.0f, 1.0f + __expf(-x));
}

// tanh(x) = 1 - 2/(1+e^{2x}). Safe at extremes (e->inf -> 1, e->0 -> -1).
__device__ __forceinline__ float tanh_f(float x) {
    return 1.0f - 2.0f * __fdividef(1.0f, 1.0f + __expf(2.0f * x));
}

__global__ __launch_bounds__(128) void lstm2_kernel(
    const float* __restrict__ x,
    const float* __restrict__ wih0, const float* __restrict__ whh0,
    const float* __restrict__ bi0,  const float* __restrict__ bh0,
    const float* __restrict__ wih1, const float* __restrict__ whh1,
    const float* __restrict__ bi1,  const float* __restrict__ bh1,
    float* __restrict__ out)
{
    const int tid = blockIdx.x * blockDim.x + threadIdx.x;
    const int b   = tid >> 3;          // batch element (group of 8 lanes)
    const int j   = tid & 7;           // hidden index role
    const bool active = (j < 6);

    // ---- Load weights into registers (packed f32x2 pairs). Inactive lanes get zeros.
    unsigned long long Wi0[4][3], Wh0[4][3], Wi1[4][3], Wh1[4][3];
    float B0[4], B1[4];
    const int jj = active ? j : 0;
    const float m = active ? 1.0f : 0.0f;
#pragma unroll
    for (int g = 0; g < 4; g++) {
        const int r = g * 6 + jj;      // gate row (i,f,g,o blocks of 6)
#pragma unroll
        for (int p = 0; p < 3; p++) {
            Wi0[g][p] = pack2(m * wih0[r * 6 + 2 * p], m * wih0[r * 6 + 2 * p + 1]);
            Wh0[g][p] = pack2(m * whh0[r * 6 + 2 * p], m * whh0[r * 6 + 2 * p + 1]);
            Wi1[g][p] = pack2(m * wih1[r * 6 + 2 * p], m * wih1[r * 6 + 2 * p + 1]);
            Wh1[g][p] = pack2(m * whh1[r * 6 + 2 * p], m * whh1[r * 6 + 2 * p + 1]);
        }
        B0[g] = m * (bi0[r] + bh0[r]);
        B1[g] = m * (bi1[r] + bh1[r]);
    }

    // ---- Recurrent state (hA/hB are full 6-vectors, packed; c is thread-local)
    unsigned long long hA[3] = {0ull, 0ull, 0ull};   // layer-0 hidden
    unsigned long long hB[3] = {0ull, 0ull, 0ull};   // layer-1 hidden
    float c0 = 0.0f, c1 = 0.0f;

    const float2* xp = reinterpret_cast<const float2*>(x) + (size_t)b * (T_STEPS * 3);
    float* op = out + (size_t)b * (T_STEPS * 6) + j;

#pragma unroll 2
    for (int t = 0; t < T_STEPS; t++) {
        // x_t : 6 contiguous floats -> 3 packed pairs (8B-aligned)
        const float2 a0 = xp[0], a1 = xp[1], a2 = xp[2];
        xp += 3;
        const unsigned long long x0 = pack2(a0.x, a0.y);
        const unsigned long long x1 = pack2(a1.x, a1.y);
        const unsigned long long x2 = pack2(a2.x, a2.y);

        // ===== layer 0 =====
        float gv0[4];
#pragma unroll
        for (int g = 0; g < 4; g++) {
            unsigned long long acc = pack2(B0[g], 0.0f);
            acc = ffma2(Wi0[g][0], x0, acc);
            acc = ffma2(Wi0[g][1], x1, acc);
            acc = ffma2(Wi0[g][2], x2, acc);
            acc = ffma2(Wh0[g][0], hA[0], acc);
            acc = ffma2(Wh0[g][1], hA[1], acc);
            acc = ffma2(Wh0[g][2], hA[2], acc);
            float lo, hi;
            unpack2(acc, lo, hi);
            gv0[g] = lo + hi;
        }
        {
            const float ig = sigmoid_f(gv0[0]);
            const float fg = sigmoid_f(gv0[1]);
            const float gg = tanh_f(gv0[2]);
            const float og = sigmoid_f(gv0[3]);
            c0 = fg * c0 + ig * gg;
            const float h0j = og * tanh_f(c0);
            // broadcast h0 across the 8-lane group (only lanes 0..5 hold data)
            const float e0 = __shfl_sync(0xffffffffu, h0j, 0, 8);
            const float e1 = __shfl_sync(0xffffffffu, h0j, 1, 8);
            const float e2 = __shfl_sync(0xffffffffu, h0j, 2, 8);
            const float e3 = __shfl_sync(0xffffffffu, h0j, 3, 8);
            const float e4 = __shfl_sync(0xffffffffu, h0j, 4, 8);
            const float e5 = __shfl_sync(0xffffffffu, h0j, 5, 8);
            hA[0] = pack2(e0, e1);
            hA[1] = pack2(e2, e3);
            hA[2] = pack2(e4, e5);
        }

        // ===== layer 1 (input = hA) =====
        float gv1[4];
#pragma unroll
        for (int g = 0; g < 4; g++) {
            unsigned long long acc = pack2(B1[g], 0.0f);
            acc = ffma2(Wi1[g][0], hA[0], acc);
            acc = ffma2(Wi1[g][1], hA[1], acc);
            acc = ffma2(Wi1[g][2], hA[2], acc);
            acc = ffma2(Wh1[g][0], hB[0], acc);
            acc = ffma2(Wh1[g][1], hB[1], acc);
            acc = ffma2(Wh1[g][2], hB[2], acc);
            float lo, hi;
            unpack2(acc, lo, hi);
            gv1[g] = lo + hi;
        }
        {
            const float ig = sigmoid_f(gv1[0]);
            const float fg = sigmoid_f(gv1[1]);
            const float gg = tanh_f(gv1[2]);
            const float og = sigmoid_f(gv1[3]);
            c1 = fg * c1 + ig * gg;
            const float h1j = og * tanh_f(c1);
            const float q0 = __shfl_sync(0xffffffffu, h1j, 0, 8);
            const float q1 = __shfl_sync(0xffffffffu, h1j, 1, 8);
            const float q2 = __shfl_sync(0xffffffffu, h1j, 2, 8);
            const float q3 = __shfl_sync(0xffffffffu, h1j, 3, 8);
            const float q4 = __shfl_sync(0xffffffffu, h1j, 4, 8);
            const float q5 = __shfl_sync(0xffffffffu, h1j, 5, 8);
            hB[0] = pack2(q0, q1);
            hB[1] = pack2(q2, q3);
            hB[2] = pack2(q4, q5);

            if (active) op[(size_t)t * 6] = h1j;
        }
    }
}

extern "C" void kernel_launch(void* const* d_in, const int* in_sizes, int n_in,
                              void* d_out, int out_size) {
    const float* x    = (const float*)d_in[0];
    const float* wih0 = (const float*)d_in[1];
    const float* whh0 = (const float*)d_in[2];
    const float* bi0  = (const float*)d_in[3];
    const float* bh0  = (const float*)d_in[4];
    const float* wih1 = (const float*)d_in[5];
    const float* whh1 = (const float*)d_in[6];
    const float* bi1  = (const float*)d_in[7];
    const float* bh1  = (const float*)d_in[8];
    float* out = (float*)d_out;

    // 4096 batch * 8 lanes = 32768 threads; 128/block -> 256 blocks
    lstm2_kernel<<<256, 128>>>(x, wih0, whh0, bi0, bh0,
                               wih1, whh1, bi1, bh1, out);
}